// round 1
// baseline (speedup 1.0000x reference)
#include <cuda_runtime.h>
#include <cuda_bf16.h>
#include <cstdint>

// Problem shape (fixed by the dataset)
#define BB 64
#define CC 256
#define HH 80
#define WW 80
#define NN 100
#define IMG 640.0f

// SMEM row stride: 84 floats keeps float4 alignment (84 % 4 == 0) and is
// conflict-free for both access patterns:
//  - column pass: S[y*84 + t], consecutive t -> consecutive banks
//  - row pass (float4): bank phase (21*t*4 + 4g) distinct within each 8-thread phase
#define SSTRIDE 84

__global__ __launch_bounds__(128, 8)
void roi_pool_kernel(const float* __restrict__ fmap,
                     const float* __restrict__ boxes,
                     float* __restrict__ out)
{
    __shared__ float S[HH * SSTRIDE];  // 80*84*4 = 26.25 KB

    const int c = blockIdx.x;   // channel
    const int b = blockIdx.y;   // batch
    const int t = threadIdx.x;  // 128 threads

    const float* plane = fmap + ((size_t)(b * CC + c)) * (HH * WW);

    // ---- Pass 1: cumulative sum over y (axis=2) fused with the global load.
    // Thread t owns column t. Coalesced: at fixed y, threads 0..79 read
    // consecutive addresses (320B).
    if (t < WW) {
        float acc = 0.0f;
        #pragma unroll
        for (int y = 0; y < HH; ++y) {
            acc += __ldg(plane + y * WW + t);
            S[y * SSTRIDE + t] = acc;
        }
    }
    __syncthreads();

    // ---- Pass 2: cumulative sum over x (axis=3), per row, float4 vectorized.
    // Thread t owns row t. S becomes the INCLUSIVE integral image:
    // S[y][x] = sum over rows<=y, cols<=x of fmap.
    if (t < HH) {
        float* row = S + t * SSTRIDE;
        float acc = 0.0f;
        #pragma unroll
        for (int g = 0; g < WW / 4; ++g) {
            float4 v = *reinterpret_cast<float4*>(row + 4 * g);
            v.x += acc;
            v.y += v.x;
            v.z += v.y;
            v.w += v.z;
            acc = v.w;
            *reinterpret_cast<float4*>(row + 4 * g) = v;
        }
    }
    __syncthreads();

    // ---- Pass 3: evaluate all 100 boxes of batch b for this channel.
    if (t < NN) {
        // boxes[b, n, 0..3] = x1f, y1f, x2f, y2f  (16B aligned -> float4)
        float4 bx = reinterpret_cast<const float4*>(boxes)[b * NN + t];

        // Exactly reference math: (coord / 640) * 80, float32 round-to-nearest
        // at each step, then int32 truncation (non-negative => floor), clip.
        int x1 = (int)__fmul_rn(__fdiv_rn(bx.x, IMG), (float)WW);
        int y1 = (int)__fmul_rn(__fdiv_rn(bx.y, IMG), (float)HH);
        int x2 = (int)__fmul_rn(__fdiv_rn(bx.z, IMG), (float)WW);
        int y2 = (int)__fmul_rn(__fdiv_rn(bx.w, IMG), (float)HH);
        x1 = min(max(x1, 0), WW);
        y1 = min(max(y1, 0), HH);
        x2 = min(max(x2, 0), WW);
        y2 = min(max(y2, 0), HH);

        const int dy = y2 - y1;
        const int dx = x2 - x1;

        float r = 0.0f;
        if (dy > 0 && dx > 0) {
            // Inclusive integral -> exclusive corners at (y-1, x-1), zero if OOB.
            // S[y2,x2] - S[y1,x2] - S[y2,x1] + S[y1,x1] with border zeros.
            float s22 = S[(y2 - 1) * SSTRIDE + (x2 - 1)];
            float s12 = (y1 > 0) ? S[(y1 - 1) * SSTRIDE + (x2 - 1)] : 0.0f;
            float s21 = (x1 > 0) ? S[(y2 - 1) * SSTRIDE + (x1 - 1)] : 0.0f;
            float s11 = (y1 > 0 && x1 > 0) ? S[(y1 - 1) * SSTRIDE + (x1 - 1)] : 0.0f;
            float ssum = s22 - s12 - s21 + s11;
            r = __fdiv_rn(ssum, (float)(dy * dx));
        }
        // out[b, n, c]; every element written exactly once (d_out is poisoned).
        out[((size_t)b * NN + t) * CC + c] = r;
    }
}

extern "C" void kernel_launch(void* const* d_in, const int* in_sizes, int n_in,
                              void* d_out, int out_size)
{
    const float* fmap  = (const float*)d_in[0];   // [64,256,80,80]
    const float* boxes = (const float*)d_in[1];   // [64,100,4]
    float* out = (float*)d_out;                   // [64,100,256]

    dim3 grid(CC, BB);   // (256, 64) -> one CTA per (b, c) plane
    dim3 block(128);
    roi_pool_kernel<<<grid, block>>>(fmap, boxes, out);
}